// round 16
// baseline (speedup 1.0000x reference)
#include <cuda_runtime.h>
#include <cuda_fp16.h>
#include <math.h>

#define Bv  4
#define Nn  24
#define NTT 16
#define TSS 48
#define TT  64
#define THR 384
#define NL  (Nn - 1)          // 23 l-slots per batch
#define GPAD 148              // padded grid: >=148 disables the low-grid issue throttle
#define SNAN 0x7fc00000u      // Ssc "not ready" sentinel
#define ESCALE 4096.0f
#define EINV   (1.0f / 4096.0f)

typedef unsigned long long u64;

// ---- packed fp32x2 helpers (sm_103a) ----
__device__ __forceinline__ u64 ffma2(u64 a, u64 b, u64 c) {
    u64 d;
    asm("fma.rn.f32x2 %0, %1, %2, %3;" : "=l"(d) : "l"(a), "l"(b), "l"(c));
    return d;
}
__device__ __forceinline__ u64 pack2(float x, float y) {
    u64 d;
    asm("mov.b64 %0, {%1, %2};" : "=l"(d) : "f"(x), "f"(y));
    return d;
}
__device__ __forceinline__ float2 unpack2(u64 v) {
    float2 f;
    asm("mov.b64 {%0, %1}, %2;" : "=f"(f.x), "=f"(f.y) : "l"(v));
    return f;
}

// ---- fast exp: magic-number round + deg-5 Taylor (rel err ~2.4e-6) ----
__device__ __forceinline__ float fexp(float x) {
    x = fmaxf(x, -80.f);
    float k  = fmaf(x, 1.4426950408889634f, 12582912.f);
    int   n  = __float_as_int(k) - 0x4B400000;
    float nf = k - 12582912.f;
    float f  = fmaf(x, 1.4426950408889634f, -nf);
    float p  = 0.0013333558f;
    p = fmaf(p, f, 0.0096181291f);
    p = fmaf(p, f, 0.0555041086f);
    p = fmaf(p, f, 0.2402265069f);
    p = fmaf(p, f, 0.6931471806f);
    p = fmaf(p, f, 1.0f);
    return p * __int_as_float((n + 127) << 23);
}

// ---- release/acquire publish primitives (GPU scope, cumulative) ----
__device__ __forceinline__ void st_release_gpu(float* p, float v) {
    asm volatile("st.release.gpu.global.b32 [%0], %1;" :: "l"(p), "f"(v) : "memory");
}
__device__ __forceinline__ float ld_acquire_gpu(const float* p) {
    float v;
    asm volatile("ld.acquire.gpu.global.b32 %0, [%1];" : "=f"(v) : "l"(p) : "memory");
    return v;
}

// ---------------- device scratch ----------------
__device__ __align__(16) __half d_E0h[Bv][Nn][256][NTT];   // exp(R0)*4096, [b][h][sc][a] fp16
__device__ __align__(16) __half d_E1h[Bv][Nn][256][NTT];
__device__ __align__(16) float d_U0t [Bv][Nn][Nn][NTT][NTT];  // [b][h][k][s][a]
__device__ __align__(16) float d_U1t [Bv][Nn][Nn][NTT][NTT];  // [b][h][k][c][a]
__device__ __align__(16) float d_V0t [Bv][Nn][TT][NTT];       // [b][h][c][a]
__device__ __align__(16) float d_V1t [Bv][Nn][TT][NTT];       // [b][h][s][a]
__device__ float d_beta [Bv][Nn+1][Nn+1][NTT][Nn];
__device__ float d_betau[Bv][Nn+1][Nn+1][NTT];
__device__ float d_Ssc  [Bv][Nn+1][Nn+1];

// ---------------- kernel 1: rule precompute + Ssc sentinel fill ----------------
__global__ void __launch_bounds__(256) k_pre(const float* __restrict__ rule,
                                             const float* __restrict__ unary) {
    int blk = blockIdx.x;
    int h = blk % Nn;
    int a = (blk / Nn) % NTT;
    int b = blk / (Nn * NTT);
    const float4* R4 = (const float4*)(rule + (size_t)((b * NTT + a) * Nn + h) * (TT * TT * 2));

    __shared__ float Er0[TT][65];   // padded: kills 16-way LDS conflict in U loops
    __shared__ float Er1[TT][65];
    __shared__ float eus[Nn][49];
    int tid = threadIdx.x;

    if (blk == 0) {  // sentinel-fill Ssc (doubles as dataflow flag); stream-ordered before k_chart
        for (int i = tid; i < Bv * (Nn + 1) * (Nn + 1); i += 256)
            ((unsigned*)&d_Ssc[0][0][0])[i] = SNAN;
    }

    // float4 = {R0[i], R1[i], R0[i+1], R1[i+1]} for even i
    #pragma unroll 4
    for (int e = tid; e < TT * TT / 2; e += 256) {
        float4 v = R4[e];
        int i = e * 2;
        int s = i >> 6, c = i & 63;
        Er0[s][c]     = fexp(v.x);
        Er1[s][c]     = fexp(v.y);
        Er0[s][c + 1] = fexp(v.z);
        Er1[s][c + 1] = fexp(v.w);
    }
    for (int t = tid; t < Nn * TSS; t += 256) {
        int k = t / TSS, c = t % TSS;
        eus[k][c] = fexp(unary[(b * Nn + k) * TT + NTT + c]);
    }
    __syncthreads();

    {
        int s = tid >> 4, c = tid & 15;
        d_E0h[b][h][s * 16 + c][a] = __float2half_rn(Er0[s][c] * ESCALE);
        d_E1h[b][h][s * 16 + c][a] = __float2half_rn(Er1[s][c] * ESCALE);
    }
    if (tid < 128) {
        int x = tid & 63;
        float acc = 0.f;
        if (tid < 64) {
            #pragma unroll 8
            for (int s = NTT; s < TT; s++) acc += Er0[s][x];
            d_V0t[b][h][x][a] = acc;
        } else {
            #pragma unroll 8
            for (int c = NTT; c < TT; c++) acc += Er1[x][c];
            d_V1t[b][h][x][a] = acc;
        }
    }
    if (tid < 192) {
        int which = tid / 96;
        int g = tid % 96;
        int x = g & 15, k0 = (g >> 4) * 4;
        float a0 = 0.f, a1 = 0.f, a2 = 0.f, a3 = 0.f;
        if (which == 0) {
            #pragma unroll 8
            for (int c = 0; c < TSS; c++) {
                float e = Er0[x][NTT + c];
                a0 += e * eus[k0 + 0][c];
                a1 += e * eus[k0 + 1][c];
                a2 += e * eus[k0 + 2][c];
                a3 += e * eus[k0 + 3][c];
            }
            d_U0t[b][h][k0 + 0][x][a] = a0;
            d_U0t[b][h][k0 + 1][x][a] = a1;
            d_U0t[b][h][k0 + 2][x][a] = a2;
            d_U0t[b][h][k0 + 3][x][a] = a3;
        } else {
            #pragma unroll 8
            for (int s = 0; s < TSS; s++) {
                float e = Er1[NTT + s][x];
                a0 += e * eus[k0 + 0][s];
                a1 += e * eus[k0 + 1][s];
                a2 += e * eus[k0 + 2][s];
                a3 += e * eus[k0 + 3][s];
            }
            d_U1t[b][h][k0 + 0][x][a] = a0;
            d_U1t[b][h][k0 + 1][x][a] = a1;
            d_U1t[b][h][k0 + 2][x][a] = a2;
            d_U1t[b][h][k0 + 3][x][a] = a3;
        }
    }
}

// spin until Ssc published (acquire semantics); pure poll
__device__ __forceinline__ float spin_ssc(const float* p) {
    float v = ld_acquire_gpu(p);
    while (__float_as_uint(v) == SNAN) {
        v = ld_acquire_gpu(p);
    }
    return v;
}

// per-warp spin + split-weight computation; returns this lane's wspe value,
// writes sref_s (thread tid==0). Ends with a warp fence so every lane's
// subsequent loads are ordered after all lanes' acquires.
__device__ __forceinline__ float warp_wspe(int W, int b, int l, int r,
                                           const float* ownS, float* sref_s,
                                           int tid) {
    int j = tid & 31;
    float v = -1e30f;
    if (j <= W - 2) {
        float sl = (j == 0)     ? 0.f : ownS[j + 1];
        float sr = (j == W - 2) ? 0.f : spin_ssc(&d_Ssc[b][l + 1 + j][r]);
        v = sl + sr;
    }
    float mx = v;
    #pragma unroll
    for (int o = 16; o > 0; o >>= 1) mx = fmaxf(mx, __shfl_xor_sync(0xffffffffu, mx, o));
    float w = (j <= W - 2) ? expf(v - mx) : 0.f;
    if (tid == 0) *sref_s = mx;
    __syncwarp();   // warp-level memory fence: propagate all lanes' acquires
    return w;
}

// ---------------- kernel 2: dataflow chart kernel ----------------
__global__ void __launch_bounds__(THR, 1) k_chart(const float* __restrict__ unary,
                                                  const float* __restrict__ root,
                                                  float* __restrict__ out) {
    // grid padded to GPAD=148 to disable the low-grid SM issue throttle
    // (B300: large-body kernels at grid<148 are issue-throttled; vanishes at >=148)
    if (blockIdx.x >= Bv * NL) return;

    extern __shared__ float dyn[];
    float* P0f  = dyn;                       // [24][264] fp32, row = hh, col = sc
    float* P1f  = dyn + 24 * 264;            // [24][264]
    float* ownB = dyn + 2 * 24 * 264;        // [23][16][24] fp32, slot = width-2
    __shared__ float eu_s[Nn][TT];
    __shared__ __align__(16) float wRTi[NTT][24][2];   // [c][jj]{w0, w1} interleaved
    __shared__ float BL2s[NTT][Nn];
    __shared__ float tmpsm[NTT][Nn];
    __shared__ float ownBu[Nn][NTT];   // slot = width-2
    __shared__ float ownS[Nn + 1];     // own Ssc by width
    __shared__ float buR0s[NTT];       // wspe[0]   * betau(l+1, r)
    __shared__ float buLW[NTT];        // wspe[W-2] * ownBu(l, r-1)
    __shared__ unsigned Msm_u;         // cell max as uint (tvals >= 0)
    __shared__ float sref_s;

    int tid = threadIdx.x;
    int b = blockIdx.x / NL;
    int l = blockIdx.x % NL;

    for (int t = tid; t < Nn * TT; t += THR)
        (&eu_s[0][0])[t] = fexp(unary[b * Nn * TT + t]);
    for (int t = tid; t < 8832; t += THR) ownB[t] = 0.f;
    if (tid < 2) ownS[tid] = 0.f;
    if (tid == 32) Msm_u = 0u;
    __syncthreads();

    int Wmax = Nn - l;
    for (int W = 2; W <= Wmax; W++) {
        int r = l + W;
        int nT = NTT * W;
        int a = tid & 15, hh = tid >> 4;
        float wl = 0.f;   // this lane's wspe value (per-warp redundant)

        if (W >= 4) {
            // ======== phase A (no block barrier before it) ========
            wl = warp_wspe(W, b, l, r, ownS, &sref_s, tid);

            // weight tables + boundary child data (uses own-warp wspe via shfl)
            {
                int c = tid / 24, jj = tid % 24;   // THR == 16*24
                int j = jj + 1;
                bool in = (j <= W - 3);
                float wj = __shfl_sync(0xffffffffu, wl, j & 31);
                wRTi[c][jj][0] = in ? wj * __ldcg(&d_betau[b][l + 1 + j][r][c]) : 0.f;
                wRTi[c][jj][1] = in ? wj * ownBu[j - 1][c] : 0.f;
            }
            if (tid < nT) {
                int c2 = tid / W, h2 = tid % W;
                BL2s[c2][h2] = __ldcg(&d_beta[b][l + 1][r][c2][l + h2]);
            }
            if (tid >= 352) {
                float w0  = __shfl_sync(0xffffffffu, wl, 0);
                float wW2 = __shfl_sync(0xffffffffu, wl, W - 2);
                int c = tid - 352;
                if (c < NTT) {
                    buR0s[c] = w0  * __ldcg(&d_betau[b][l + 1][r][c]);
                    buLW[c]  = wW2 * ownBu[W - 3][c];
                }
            }

            // hoisted P-build child loads (need only the acquire, done per-warp)
            u64 bvp[24];
            int phh = tid % W, x = tid / W;
            if (tid < nT) {
                #pragma unroll
                for (int j = 1; j <= 24; j++) {
                    if (j <= W - 3) {
                        float bl = ownB[(j - 1) * 384 + x * 24 + phh];
                        float br = __ldcg(&d_beta[b][l + 1 + j][r][x][l + phh]);
                        bvp[j - 1] = pack2(bl, br);
                    } else bvp[j - 1] = 0ULL;
                }
            }
            __syncthreads();   // bar 1

            // ======== P-build FMA: both tables fused via FFMA2 ========
            if (tid < nT) {
                #pragma unroll
                for (int c = 0; c < NTT; c++) {
                    u64 acc = 0ULL;
                    #pragma unroll
                    for (int k = 0; k < 6; k++) {
                        if (4 * k <= W - 4) {   // warp-uniform
                            const u64* wp = reinterpret_cast<const u64*>(&wRTi[c][4 * k][0]);
                            acc = ffma2(bvp[4 * k + 0], wp[0], acc);
                            acc = ffma2(bvp[4 * k + 1], wp[1], acc);
                            acc = ffma2(bvp[4 * k + 2], wp[2], acc);
                            acc = ffma2(bvp[4 * k + 3], wp[3], acc);
                        }
                    }
                    float2 pv = unpack2(acc);
                    P0f[phh * 264 + x * 16 + c] = pv.x;
                    P1f[phh * 264 + c * 16 + x] = pv.y;
                }
            }
            __syncthreads();   // bar 2

            // ======== contraction + folded boundary + per-warp max ========
            {
                int wd = tid >> 5, lane = tid & 31;
                int sc_lo = lane >> 1, a8 = lane & 1;
                float wspe0  = __shfl_sync(0xffffffffu, wl, 0);
                float wspeW2 = __shfl_sync(0xffffffffu, wl, W - 2);
                float wmax = 0.f;
                for (int chh = wd; chh < W; chh += 12) {
                    const uint4* E0 = reinterpret_cast<const uint4*>(&d_E0h[b][l + chh][0][0]);
                    const uint4* E1 = reinterpret_cast<const uint4*>(&d_E1h[b][l + chh][0][0]);
                    const float* p0 = P0f + chh * 264;
                    const float* p1 = P1f + chh * 264;
                    float acc[8];
                    #pragma unroll
                    for (int k = 0; k < 8; k++) acc[k] = 0.f;
                    #pragma unroll
                    for (int i = 0; i < 16; i++) {
                        int sc = i * 16 + sc_lo;
                        float v0 = p0[sc];
                        float v1 = p1[sc];
                        uint4 e0 = __ldg(E0 + sc * 2 + a8);
                        uint4 e1 = __ldg(E1 + sc * 2 + a8);
                        float2 f;
                        f = __half22float2(*reinterpret_cast<const __half2*>(&e0.x));
                        acc[0] = fmaf(v0, f.x, acc[0]); acc[1] = fmaf(v0, f.y, acc[1]);
                        f = __half22float2(*reinterpret_cast<const __half2*>(&e0.y));
                        acc[2] = fmaf(v0, f.x, acc[2]); acc[3] = fmaf(v0, f.y, acc[3]);
                        f = __half22float2(*reinterpret_cast<const __half2*>(&e0.z));
                        acc[4] = fmaf(v0, f.x, acc[4]); acc[5] = fmaf(v0, f.y, acc[5]);
                        f = __half22float2(*reinterpret_cast<const __half2*>(&e0.w));
                        acc[6] = fmaf(v0, f.x, acc[6]); acc[7] = fmaf(v0, f.y, acc[7]);
                        f = __half22float2(*reinterpret_cast<const __half2*>(&e1.x));
                        acc[0] = fmaf(v1, f.x, acc[0]); acc[1] = fmaf(v1, f.y, acc[1]);
                        f = __half22float2(*reinterpret_cast<const __half2*>(&e1.y));
                        acc[2] = fmaf(v1, f.x, acc[2]); acc[3] = fmaf(v1, f.y, acc[3]);
                        f = __half22float2(*reinterpret_cast<const __half2*>(&e1.z));
                        acc[4] = fmaf(v1, f.x, acc[4]); acc[5] = fmaf(v1, f.y, acc[5]);
                        f = __half22float2(*reinterpret_cast<const __half2*>(&e1.w));
                        acc[6] = fmaf(v1, f.x, acc[6]); acc[7] = fmaf(v1, f.y, acc[7]);
                    }
                    // folded boundary terms (fp32 tables, weights pre-scaled by ESCALE)
                    {   // s2: U1(l+hh, k=l) . (wspe0 * BL2)
                        float v = wspe0 * ESCALE * BL2s[sc_lo][chh];
                        const float4* U1 = reinterpret_cast<const float4*>(
                            &d_U1t[b][l + chh][l][sc_lo][a8 * 8]);
                        float4 ua = __ldg(U1), ub = __ldg(U1 + 1);
                        acc[0] = fmaf(v, ua.x, acc[0]); acc[1] = fmaf(v, ua.y, acc[1]);
                        acc[2] = fmaf(v, ua.z, acc[2]); acc[3] = fmaf(v, ua.w, acc[3]);
                        acc[4] = fmaf(v, ub.x, acc[4]); acc[5] = fmaf(v, ub.y, acc[5]);
                        acc[6] = fmaf(v, ub.z, acc[6]); acc[7] = fmaf(v, ub.w, acc[7]);
                    }
                    {   // s3: U0(l+hh, k=r-1) . (wspeW2 * ownB(l, r-1))
                        float v = wspeW2 * ESCALE * ownB[(W - 3) * 384 + sc_lo * 24 + chh];
                        const float4* U0 = reinterpret_cast<const float4*>(
                            &d_U0t[b][l + chh][r - 1][sc_lo][a8 * 8]);
                        float4 ua = __ldg(U0), ub = __ldg(U0 + 1);
                        acc[0] = fmaf(v, ua.x, acc[0]); acc[1] = fmaf(v, ua.y, acc[1]);
                        acc[2] = fmaf(v, ua.z, acc[2]); acc[3] = fmaf(v, ua.w, acc[3]);
                        acc[4] = fmaf(v, ub.x, acc[4]); acc[5] = fmaf(v, ub.y, acc[5]);
                        acc[6] = fmaf(v, ub.z, acc[6]); acc[7] = fmaf(v, ub.w, acc[7]);
                    }
                    if (chh == 0) {   // s1: V0(l) . buR0s
                        float v = ESCALE * buR0s[sc_lo];
                        const float4* V0 = reinterpret_cast<const float4*>(
                            &d_V0t[b][l][sc_lo][a8 * 8]);
                        float4 ua = __ldg(V0), ub = __ldg(V0 + 1);
                        acc[0] = fmaf(v, ua.x, acc[0]); acc[1] = fmaf(v, ua.y, acc[1]);
                        acc[2] = fmaf(v, ua.z, acc[2]); acc[3] = fmaf(v, ua.w, acc[3]);
                        acc[4] = fmaf(v, ub.x, acc[4]); acc[5] = fmaf(v, ub.y, acc[5]);
                        acc[6] = fmaf(v, ub.z, acc[6]); acc[7] = fmaf(v, ub.w, acc[7]);
                    }
                    if (chh == W - 1) {   // s4: V1(r-1) . buLW
                        float v = ESCALE * buLW[sc_lo];
                        const float4* V1 = reinterpret_cast<const float4*>(
                            &d_V1t[b][r - 1][sc_lo][a8 * 8]);
                        float4 ua = __ldg(V1), ub = __ldg(V1 + 1);
                        acc[0] = fmaf(v, ua.x, acc[0]); acc[1] = fmaf(v, ua.y, acc[1]);
                        acc[2] = fmaf(v, ua.z, acc[2]); acc[3] = fmaf(v, ua.w, acc[3]);
                        acc[4] = fmaf(v, ub.x, acc[4]); acc[5] = fmaf(v, ub.y, acc[5]);
                        acc[6] = fmaf(v, ub.z, acc[6]); acc[7] = fmaf(v, ub.w, acc[7]);
                    }
                    #pragma unroll
                    for (int o = 2; o <= 16; o <<= 1) {
                        #pragma unroll
                        for (int k = 0; k < 8; k++)
                            acc[k] += __shfl_xor_sync(0xffffffffu, acc[k], o);
                    }
                    if (sc_lo == 0) {
                        int abase = a8 * 8;
                        #pragma unroll
                        for (int k = 0; k < 8; k++) {
                            float tv = acc[k] * EINV;
                            tmpsm[abase + k][chh] = tv;
                            wmax = fmaxf(wmax, tv);
                        }
                    }
                }
                wmax = fmaxf(wmax, __shfl_xor_sync(0xffffffffu, wmax, 1));
                if (lane == 0 && wmax > 0.f)
                    atomicMax(reinterpret_cast<int*>(const_cast<unsigned*>(&Msm_u)),
                              (int)__float_as_uint(wmax));
            }
            __syncthreads();   // bar 3
        } else {
            // ======== W == 2 / 3 ========
            float w0 = 1.f, wW2 = 1.f;
            if (W == 3) {
                wl = warp_wspe(W, b, l, r, ownS, &sref_s, tid);
                w0  = __shfl_sync(0xffffffffu, wl, 0);
                wW2 = __shfl_sync(0xffffffffu, wl, W - 2);
                if (tid < nT) {
                    int c2 = tid / W, h2 = tid % W;
                    BL2s[c2][h2] = __ldcg(&d_beta[b][l + 1][r][c2][l + h2]);
                }
                if (tid >= 352) {
                    int c = tid - 352;
                    if (c < NTT) {
                        buR0s[c] = w0  * __ldcg(&d_betau[b][l + 1][r][c]);
                        buLW[c]  = wW2 * ownBu[W - 3][c];
                    }
                }
            } else {
                if (tid == 0) sref_s = 0.f;
            }
            __syncthreads();   // bar 1

            float tval = 0.f;
            if (tid < nT) {
                if (W == 3) {
                    float s2 = 0.f, s3 = 0.f;
                    #pragma unroll
                    for (int c = 0; c < NTT; c++) {
                        s2 += __ldg(&d_U1t[b][l + hh][l][c][a]) * BL2s[c][hh];
                        s3 += __ldg(&d_U0t[b][l + hh][r - 1][c][a]) * ownB[0 * 384 + c * 24 + hh];
                    }
                    tval = w0 * s2 + wW2 * s3;
                    if (hh == 0) {
                        float s1 = 0.f;
                        #pragma unroll
                        for (int c = 0; c < NTT; c++)
                            s1 += __ldg(&d_V0t[b][l][c][a]) * buR0s[c];
                        tval += s1;
                    }
                    if (hh == W - 1) {
                        float s4 = 0.f;
                        #pragma unroll
                        for (int c = 0; c < NTT; c++)
                            s4 += __ldg(&d_V1t[b][r - 1][c][a]) * buLW[c];
                        tval += s4;
                    }
                } else {  // W == 2
                    if (hh == 0) {
                        #pragma unroll 8
                        for (int c = 0; c < TSS; c++)
                            tval += eu_s[l + 1][NTT + c] * __ldg(&d_V0t[b][l][NTT + c][a]);
                    } else {
                        #pragma unroll 8
                        for (int c = 0; c < TSS; c++)
                            tval += eu_s[l][NTT + c] * __ldg(&d_V1t[b][l + 1][NTT + c][a]);
                    }
                }
                tmpsm[a][hh] = tval;
            }
            float wm = tval;
            #pragma unroll
            for (int o = 16; o > 0; o >>= 1) wm = fmaxf(wm, __shfl_xor_sync(0xffffffffu, wm, o));
            if ((tid & 31) == 0 && wm > 0.f)
                atomicMax(reinterpret_cast<int*>(const_cast<unsigned*>(&Msm_u)),
                          (int)__float_as_uint(wm));
            __syncthreads();   // bar 3
        }

        // ======== commit + publish ========
        float Msm = __uint_as_float(Msm_u);
        float invM = 1.f / Msm;
        {
            int ca = tid / Nn, habs = tid % Nn;   // THR == 16*24 exactly
            float v = 0.f;
            if (habs >= l && habs < r) {
                v = tmpsm[ca][habs - l] * invM;
                ownB[(W - 2) * 384 + ca * 24 + (habs - l)] = v;
            }
            __stcg(&d_beta[b][l][r][ca][habs], v);
        }
        if (tid < NTT) {
            float accu = 0.f;
            for (int h2 = 0; h2 < W; h2++)
                accu += tmpsm[tid][h2] * eu_s[l + h2][tid];
            float bu = accu * invM;
            __stcg(&d_betau[b][l][r][tid], bu);
            ownBu[W - 2][tid] = bu;
            if (W == Nn) {   // only block (b, 0): fused root reduction
                float v = bu * __expf(root[b * NTT + tid]);
                #pragma unroll
                for (int o = 8; o > 0; o >>= 1) v += __shfl_xor_sync(0xffffu, v, o);
                if (tid == 0) out[b] = sref_s + logf(Msm) + logf(v);
            }
        }
        float ss = 0.f;
        if (tid == 0) {
            ss = sref_s + logf(Msm);
            ownS[W] = ss;   // written BEFORE bar 4 so all warps may read it next cell
        }
        __syncthreads();   // bar 4: all stores + ownS ordered before release
        if (tid == 0) st_release_gpu(&d_Ssc[b][l][r], ss);
        if (tid == 32) Msm_u = 0u;   // ordered for consumers by next cell's bar 1/2
    }
}

// ---------------- launch ----------------
extern "C" void kernel_launch(void* const* d_in, const int* in_sizes, int n_in,
                              void* d_out, int out_size) {
    const float* unary = nullptr;
    const float* rule  = nullptr;
    const float* root  = nullptr;
    for (int i = 0; i < n_in; i++) {
        if (in_sizes[i] == Bv * Nn * TT)                      unary = (const float*)d_in[i];
        else if (in_sizes[i] == Bv * NTT * Nn * TT * TT * 2)  rule  = (const float*)d_in[i];
        else if (in_sizes[i] == Bv * NTT)                     root  = (const float*)d_in[i];
    }

    int dynBytes = (2 * 24 * 264 + 23 * 16 * 24) * (int)sizeof(float);  // 86016
    cudaFuncSetAttribute(k_chart, cudaFuncAttributeMaxDynamicSharedMemorySize, dynBytes);

    k_pre<<<Bv * NTT * Nn, 256>>>(rule, unary);
    k_chart<<<GPAD, THR, dynBytes>>>(unary, root, (float*)d_out);
}

// round 17
// speedup vs baseline: 1.0534x; 1.0534x over previous
#include <cuda_runtime.h>
#include <cuda_fp16.h>
#include <math.h>

#define Bv  4
#define Nn  24
#define NTT 16
#define TSS 48
#define TT  64
#define THR 384
#define NL  (Nn - 1)          // 23 l-slots per batch
#define SNAN 0x7fc00000u      // Ssc "not ready" sentinel
#define ESCALE 4096.0f
#define EINV   (1.0f / 4096.0f)

typedef unsigned long long u64;

// ---- packed fp32x2 helpers (sm_103a) ----
__device__ __forceinline__ u64 ffma2(u64 a, u64 b, u64 c) {
    u64 d;
    asm("fma.rn.f32x2 %0, %1, %2, %3;" : "=l"(d) : "l"(a), "l"(b), "l"(c));
    return d;
}
__device__ __forceinline__ u64 pack2(float x, float y) {
    u64 d;
    asm("mov.b64 %0, {%1, %2};" : "=l"(d) : "f"(x), "f"(y));
    return d;
}
__device__ __forceinline__ float2 unpack2(u64 v) {
    float2 f;
    asm("mov.b64 {%0, %1}, %2;" : "=f"(f.x), "=f"(f.y) : "l"(v));
    return f;
}

// ---- fast exp: magic-number round + deg-5 Taylor (rel err ~2.4e-6) ----
__device__ __forceinline__ float fexp(float x) {
    x = fmaxf(x, -80.f);
    float k  = fmaf(x, 1.4426950408889634f, 12582912.f);
    int   n  = __float_as_int(k) - 0x4B400000;
    float nf = k - 12582912.f;
    float f  = fmaf(x, 1.4426950408889634f, -nf);
    float p  = 0.0013333558f;
    p = fmaf(p, f, 0.0096181291f);
    p = fmaf(p, f, 0.0555041086f);
    p = fmaf(p, f, 0.2402265069f);
    p = fmaf(p, f, 0.6931471806f);
    p = fmaf(p, f, 1.0f);
    return p * __int_as_float((n + 127) << 23);
}

// ---- release/acquire publish primitives (GPU scope, cumulative) ----
__device__ __forceinline__ void st_release_gpu(float* p, float v) {
    asm volatile("st.release.gpu.global.b32 [%0], %1;" :: "l"(p), "f"(v) : "memory");
}
__device__ __forceinline__ float ld_acquire_gpu(const float* p) {
    float v;
    asm volatile("ld.acquire.gpu.global.b32 %0, [%1];" : "=f"(v) : "l"(p) : "memory");
    return v;
}

// ---------------- device scratch ----------------
__device__ __align__(16) __half d_E0h[Bv][Nn][256][NTT];   // exp(R0)*4096, [b][h][sc][a] fp16
__device__ __align__(16) __half d_E1h[Bv][Nn][256][NTT];
__device__ __align__(16) float d_U0t [Bv][Nn][Nn][NTT][NTT];  // [b][h][k][s][a]
__device__ __align__(16) float d_U1t [Bv][Nn][Nn][NTT][NTT];  // [b][h][k][c][a]
__device__ __align__(16) float d_V0t [Bv][Nn][TT][NTT];       // [b][h][c][a]
__device__ __align__(16) float d_V1t [Bv][Nn][TT][NTT];       // [b][h][s][a]
__device__ float d_beta [Bv][Nn+1][Nn+1][NTT][Nn];
__device__ float d_betau[Bv][Nn+1][Nn+1][NTT];
__device__ float d_Ssc  [Bv][Nn+1][Nn+1];

// ---------------- kernel 1: rule precompute + Ssc sentinel fill ----------------
__global__ void __launch_bounds__(256) k_pre(const float* __restrict__ rule,
                                             const float* __restrict__ unary) {
    int blk = blockIdx.x;
    int h = blk % Nn;
    int a = (blk / Nn) % NTT;
    int b = blk / (Nn * NTT);
    const float4* R4 = (const float4*)(rule + (size_t)((b * NTT + a) * Nn + h) * (TT * TT * 2));

    __shared__ float Er0[TT][65];
    __shared__ float Er1[TT][65];
    __shared__ float eus[Nn][49];
    int tid = threadIdx.x;

    if (blk == 0) {
        for (int i = tid; i < Bv * (Nn + 1) * (Nn + 1); i += 256)
            ((unsigned*)&d_Ssc[0][0][0])[i] = SNAN;
    }

    #pragma unroll 4
    for (int e = tid; e < TT * TT / 2; e += 256) {
        float4 v = R4[e];
        int i = e * 2;
        int s = i >> 6, c = i & 63;
        Er0[s][c]     = fexp(v.x);
        Er1[s][c]     = fexp(v.y);
        Er0[s][c + 1] = fexp(v.z);
        Er1[s][c + 1] = fexp(v.w);
    }
    for (int t = tid; t < Nn * TSS; t += 256) {
        int k = t / TSS, c = t % TSS;
        eus[k][c] = fexp(unary[(b * Nn + k) * TT + NTT + c]);
    }
    __syncthreads();

    {
        int s = tid >> 4, c = tid & 15;
        d_E0h[b][h][s * 16 + c][a] = __float2half_rn(Er0[s][c] * ESCALE);
        d_E1h[b][h][s * 16 + c][a] = __float2half_rn(Er1[s][c] * ESCALE);
    }
    if (tid < 128) {
        int x = tid & 63;
        float acc = 0.f;
        if (tid < 64) {
            #pragma unroll 8
            for (int s = NTT; s < TT; s++) acc += Er0[s][x];
            d_V0t[b][h][x][a] = acc;
        } else {
            #pragma unroll 8
            for (int c = NTT; c < TT; c++) acc += Er1[x][c];
            d_V1t[b][h][x][a] = acc;
        }
    }
    if (tid < 192) {
        int which = tid / 96;
        int g = tid % 96;
        int x = g & 15, k0 = (g >> 4) * 4;
        float a0 = 0.f, a1 = 0.f, a2 = 0.f, a3 = 0.f;
        if (which == 0) {
            #pragma unroll 8
            for (int c = 0; c < TSS; c++) {
                float e = Er0[x][NTT + c];
                a0 += e * eus[k0 + 0][c];
                a1 += e * eus[k0 + 1][c];
                a2 += e * eus[k0 + 2][c];
                a3 += e * eus[k0 + 3][c];
            }
            d_U0t[b][h][k0 + 0][x][a] = a0;
            d_U0t[b][h][k0 + 1][x][a] = a1;
            d_U0t[b][h][k0 + 2][x][a] = a2;
            d_U0t[b][h][k0 + 3][x][a] = a3;
        } else {
            #pragma unroll 8
            for (int s = 0; s < TSS; s++) {
                float e = Er1[NTT + s][x];
                a0 += e * eus[k0 + 0][s];
                a1 += e * eus[k0 + 1][s];
                a2 += e * eus[k0 + 2][s];
                a3 += e * eus[k0 + 3][s];
            }
            d_U1t[b][h][k0 + 0][x][a] = a0;
            d_U1t[b][h][k0 + 1][x][a] = a1;
            d_U1t[b][h][k0 + 2][x][a] = a2;
            d_U1t[b][h][k0 + 3][x][a] = a3;
        }
    }
}

// spin until Ssc published (acquire semantics); pure poll
__device__ __forceinline__ float spin_ssc(const float* p) {
    float v = ld_acquire_gpu(p);
    while (__float_as_uint(v) == SNAN) {
        v = ld_acquire_gpu(p);
    }
    return v;
}

// per-warp partial split weights over j in [1, W-2] (EXCLUDES the critical j=0
// child). Returns this lane's weight; *mx_out = provisional sref1 (all lanes).
__device__ __forceinline__ float warp_wspe1(int W, int b, int l, int r,
                                            const float* ownS, float* mx_out,
                                            int tid) {
    int j = tid & 31;
    float v = -1e30f;
    bool act = (j >= 1 && j <= W - 2);
    if (act) {
        float sl = ownS[j + 1];
        float sr = (j == W - 2) ? 0.f : spin_ssc(&d_Ssc[b][l + 1 + j][r]);
        v = sl + sr;
    }
    float mx = v;
    #pragma unroll
    for (int o = 16; o > 0; o >>= 1) mx = fmaxf(mx, __shfl_xor_sync(0xffffffffu, mx, o));
    float w = act ? expf(v - mx) : 0.f;
    *mx_out = mx;
    __syncwarp();   // propagate all lanes' acquires within the warp
    return w;
}

// ---------------- kernel 2: dataflow chart kernel (deferred critical child) ----------------
__global__ void __launch_bounds__(THR, 1) k_chart(const float* __restrict__ unary,
                                                  const float* __restrict__ root,
                                                  float* __restrict__ out) {
    extern __shared__ float dyn[];
    float* P0f  = dyn;                       // [24][264] fp32, row = hh, col = sc
    float* P1f  = dyn + 24 * 264;            // [24][264]
    float* ownB = dyn + 2 * 24 * 264;        // [23][16][24] fp32, slot = width-2
    __shared__ float eu_s[Nn][TT];
    __shared__ __align__(16) float wRTi[NTT][24][2];   // [c][jj]{w0, w1} interleaved
    __shared__ float tmpsm[NTT][Nn];
    __shared__ float ownBu[Nn][NTT];   // slot = width-2
    __shared__ float ownS[Nn + 1];     // own Ssc by width
    __shared__ float buLW[NTT];        // wspe[W-2] * ownBu(l, r-1)
    __shared__ unsigned Msm_u;         // cell max as uint (tvals >= 0)

    int tid = threadIdx.x;
    int b = blockIdx.x / NL;
    int l = blockIdx.x % NL;

    for (int t = tid; t < Nn * TT; t += THR)
        (&eu_s[0][0])[t] = fexp(unary[b * Nn * TT + t]);
    for (int t = tid; t < 8832; t += THR) ownB[t] = 0.f;
    if (tid < 2) ownS[tid] = 0.f;
    if (tid == 32) Msm_u = 0u;
    __syncthreads();

    int Wmax = Nn - l;
    for (int W = 2; W <= Wmax; W++) {
        int r = l + W;
        int nT = NTT * W;
        int a = tid & 15, hh = tid >> 4;
        float wl = 0.f;      // lane's wspe (provisional scale)
        float mx1 = 0.f;     // provisional sref1 (per-thread)
        float tv1 = 0.f;     // provisional tval (W==3 path keeps in register)
        float srefF = 0.f;   // final sref

        if (W >= 4) {
            // ======== phase A: everything independent of (l+1, r) ========
            wl = warp_wspe1(W, b, l, r, ownS, &mx1, tid);

            {   // interleaved weight tables (j in 1..W-3)
                int c = tid / 24, jj = tid % 24;   // THR == 16*24
                int j = jj + 1;
                bool in = (j <= W - 3);
                float wj = __shfl_sync(0xffffffffu, wl, j & 31);
                wRTi[c][jj][0] = (in && j >= 1) ? wj * __ldcg(&d_betau[b][l + 1 + j][r][c]) : 0.f;
                wRTi[c][jj][1] = (in && j >= 1) ? wj * ownBu[j - 1][c] : 0.f;
            }
            if (tid >= 352) {
                float wW2 = __shfl_sync(0xffffffffu, wl, W - 2);
                int c = tid - 352;
                if (c < NTT) buLW[c] = wW2 * ownBu[W - 3][c];
            }

            // hoisted P-build child loads (children j>=1 only)
            u64 bvp[24];
            int phh = tid % W, x = tid / W;
            if (tid < nT) {
                #pragma unroll
                for (int j = 1; j <= 24; j++) {
                    if (j <= W - 3) {
                        float bl = ownB[(j - 1) * 384 + x * 24 + phh];
                        float br = __ldcg(&d_beta[b][l + 1 + j][r][x][l + phh]);
                        bvp[j - 1] = pack2(bl, br);
                    } else bvp[j - 1] = 0ULL;
                }
            }
            __syncthreads();   // bar 1

            // ======== P-build FMA: both tables fused via FFMA2 ========
            if (tid < nT) {
                #pragma unroll
                for (int c = 0; c < NTT; c++) {
                    u64 acc = 0ULL;
                    #pragma unroll
                    for (int k = 0; k < 6; k++) {
                        if (4 * k <= W - 4) {   // warp-uniform
                            const u64* wp = reinterpret_cast<const u64*>(&wRTi[c][4 * k][0]);
                            acc = ffma2(bvp[4 * k + 0], wp[0], acc);
                            acc = ffma2(bvp[4 * k + 1], wp[1], acc);
                            acc = ffma2(bvp[4 * k + 2], wp[2], acc);
                            acc = ffma2(bvp[4 * k + 3], wp[3], acc);
                        }
                    }
                    float2 pv = unpack2(acc);
                    P0f[phh * 264 + x * 16 + c] = pv.x;
                    P1f[phh * 264 + c * 16 + x] = pv.y;
                }
            }
            __syncthreads();   // bar 2

            // ======== contraction + folded s3/s4 -> provisional tval1 ========
            {
                int wd = tid >> 5, lane = tid & 31;
                int sc_lo = lane >> 1, a8 = lane & 1;
                float wspeW2 = __shfl_sync(0xffffffffu, wl, W - 2);
                for (int chh = wd; chh < W; chh += 12) {
                    const uint4* E0 = reinterpret_cast<const uint4*>(&d_E0h[b][l + chh][0][0]);
                    const uint4* E1 = reinterpret_cast<const uint4*>(&d_E1h[b][l + chh][0][0]);
                    const float* p0 = P0f + chh * 264;
                    const float* p1 = P1f + chh * 264;
                    float acc[8];
                    #pragma unroll
                    for (int k = 0; k < 8; k++) acc[k] = 0.f;
                    #pragma unroll
                    for (int i = 0; i < 16; i++) {
                        int sc = i * 16 + sc_lo;
                        float v0 = p0[sc];
                        float v1 = p1[sc];
                        uint4 e0 = __ldg(E0 + sc * 2 + a8);
                        uint4 e1 = __ldg(E1 + sc * 2 + a8);
                        float2 f;
                        f = __half22float2(*reinterpret_cast<const __half2*>(&e0.x));
                        acc[0] = fmaf(v0, f.x, acc[0]); acc[1] = fmaf(v0, f.y, acc[1]);
                        f = __half22float2(*reinterpret_cast<const __half2*>(&e0.y));
                        acc[2] = fmaf(v0, f.x, acc[2]); acc[3] = fmaf(v0, f.y, acc[3]);
                        f = __half22float2(*reinterpret_cast<const __half2*>(&e0.z));
                        acc[4] = fmaf(v0, f.x, acc[4]); acc[5] = fmaf(v0, f.y, acc[5]);
                        f = __half22float2(*reinterpret_cast<const __half2*>(&e0.w));
                        acc[6] = fmaf(v0, f.x, acc[6]); acc[7] = fmaf(v0, f.y, acc[7]);
                        f = __half22float2(*reinterpret_cast<const __half2*>(&e1.x));
                        acc[0] = fmaf(v1, f.x, acc[0]); acc[1] = fmaf(v1, f.y, acc[1]);
                        f = __half22float2(*reinterpret_cast<const __half2*>(&e1.y));
                        acc[2] = fmaf(v1, f.x, acc[2]); acc[3] = fmaf(v1, f.y, acc[3]);
                        f = __half22float2(*reinterpret_cast<const __half2*>(&e1.z));
                        acc[4] = fmaf(v1, f.x, acc[4]); acc[5] = fmaf(v1, f.y, acc[5]);
                        f = __half22float2(*reinterpret_cast<const __half2*>(&e1.w));
                        acc[6] = fmaf(v1, f.x, acc[6]); acc[7] = fmaf(v1, f.y, acc[7]);
                    }
                    {   // s3: U0(l+hh, k=r-1) . (wspeW2 * ownB(l, r-1))
                        float v = wspeW2 * ESCALE * ownB[(W - 3) * 384 + sc_lo * 24 + chh];
                        const float4* U0 = reinterpret_cast<const float4*>(
                            &d_U0t[b][l + chh][r - 1][sc_lo][a8 * 8]);
                        float4 ua = __ldg(U0), ub = __ldg(U0 + 1);
                        acc[0] = fmaf(v, ua.x, acc[0]); acc[1] = fmaf(v, ua.y, acc[1]);
                        acc[2] = fmaf(v, ua.z, acc[2]); acc[3] = fmaf(v, ua.w, acc[3]);
                        acc[4] = fmaf(v, ub.x, acc[4]); acc[5] = fmaf(v, ub.y, acc[5]);
                        acc[6] = fmaf(v, ub.z, acc[6]); acc[7] = fmaf(v, ub.w, acc[7]);
                    }
                    if (chh == W - 1) {   // s4: V1(r-1) . buLW
                        float v = ESCALE * buLW[sc_lo];
                        const float4* V1 = reinterpret_cast<const float4*>(
                            &d_V1t[b][r - 1][sc_lo][a8 * 8]);
                        float4 ua = __ldg(V1), ub = __ldg(V1 + 1);
                        acc[0] = fmaf(v, ua.x, acc[0]); acc[1] = fmaf(v, ua.y, acc[1]);
                        acc[2] = fmaf(v, ua.z, acc[2]); acc[3] = fmaf(v, ua.w, acc[3]);
                        acc[4] = fmaf(v, ub.x, acc[4]); acc[5] = fmaf(v, ub.y, acc[5]);
                        acc[6] = fmaf(v, ub.z, acc[6]); acc[7] = fmaf(v, ub.w, acc[7]);
                    }
                    #pragma unroll
                    for (int o = 2; o <= 16; o <<= 1) {
                        #pragma unroll
                        for (int k = 0; k < 8; k++)
                            acc[k] += __shfl_xor_sync(0xffffffffu, acc[k], o);
                    }
                    if (sc_lo == 0) {
                        int abase = a8 * 8;
                        #pragma unroll
                        for (int k = 0; k < 8; k++)
                            tmpsm[abase + k][chh] = acc[k] * EINV;   // provisional tval1
                    }
                }
            }
            __syncthreads();   // bar 3
            if (tid < nT) tv1 = tmpsm[a][hh];
        } else if (W == 3) {
            // ======== W == 3 phase A: j=1 only (known) ========
            wl = warp_wspe1(W, b, l, r, ownS, &mx1, tid);
            float w1 = __shfl_sync(0xffffffffu, wl, 1);
            if (tid < nT) {
                float s3 = 0.f;
                #pragma unroll
                for (int c = 0; c < NTT; c++)
                    s3 += __ldg(&d_U0t[b][l + hh][r - 1][c][a]) * ownB[c * 24 + hh];
                tv1 = w1 * s3;
                if (hh == W - 1) {
                    float s4 = 0.f;
                    #pragma unroll
                    for (int c = 0; c < NTT; c++)
                        s4 += __ldg(&d_V1t[b][r - 1][c][a]) * (w1 * ownBu[0][c]);
                    tv1 += s4;
                }
            }
            __syncthreads();   // orders prev cell's Msm_u reset before phase-B atomicMax
        } else {
            // ======== W == 2: both children width-1, no deps ========
            __syncthreads();   // orders prev cell's Msm_u reset
            float tval = 0.f;
            if (tid < nT) {
                if (hh == 0) {
                    #pragma unroll 8
                    for (int c = 0; c < TSS; c++)
                        tval += eu_s[l + 1][NTT + c] * __ldg(&d_V0t[b][l][NTT + c][a]);
                } else {
                    #pragma unroll 8
                    for (int c = 0; c < TSS; c++)
                        tval += eu_s[l][NTT + c] * __ldg(&d_V1t[b][l + 1][NTT + c][a]);
                }
                tmpsm[a][hh] = tval;
            }
            float wm = tval;
            #pragma unroll
            for (int o = 16; o > 0; o >>= 1) wm = fmaxf(wm, __shfl_xor_sync(0xffffffffu, wm, o));
            if ((tid & 31) == 0 && wm > 0.f)
                atomicMax(reinterpret_cast<int*>(const_cast<unsigned*>(&Msm_u)),
                          (int)__float_as_uint(wm));
            srefF = 0.f;
            __syncthreads();   // bar 3.5
        }

        // ======== phase B: fold the critical child (l+1, r) ========
        if (W >= 3) {
            float s0 = spin_ssc(&d_Ssc[b][l + 1][r]);   // each thread: own acquire
            srefF = fmaxf(mx1, s0);
            float e1 = expf(mx1 - srefF);
            float e0 = expf(s0 - srefF);
            float tval = 0.f;
            if (tid < nT) {
                float s2 = 0.f;
                #pragma unroll
                for (int c = 0; c < NTT; c++)
                    s2 += __ldg(&d_U1t[b][l + hh][l][c][a])
                        * __ldcg(&d_beta[b][l + 1][r][c][l + hh]);
                tval = tv1 * e1 + e0 * s2;
                if (hh == 0) {
                    float s1 = 0.f;
                    #pragma unroll
                    for (int c = 0; c < NTT; c++)
                        s1 += __ldg(&d_V0t[b][l][c][a]) * __ldcg(&d_betau[b][l + 1][r][c]);
                    tval += e0 * s1;
                }
                tmpsm[a][hh] = tval;
            }
            float wm = tval;
            #pragma unroll
            for (int o = 16; o > 0; o >>= 1) wm = fmaxf(wm, __shfl_xor_sync(0xffffffffu, wm, o));
            if ((tid & 31) == 0 && wm > 0.f)
                atomicMax(reinterpret_cast<int*>(const_cast<unsigned*>(&Msm_u)),
                          (int)__float_as_uint(wm));
            __syncthreads();   // bar 3.5
        }

        // ======== commit + publish ========
        float Msm = __uint_as_float(Msm_u);
        float invM = 1.f / Msm;
        {
            int ca = tid / Nn, habs = tid % Nn;   // THR == 16*24 exactly
            float v = 0.f;
            if (habs >= l && habs < r) {
                v = tmpsm[ca][habs - l] * invM;
                ownB[(W - 2) * 384 + ca * 24 + (habs - l)] = v;
            }
            __stcg(&d_beta[b][l][r][ca][habs], v);
        }
        if (tid < NTT) {
            float accu = 0.f;
            for (int h2 = 0; h2 < W; h2++)
                accu += tmpsm[tid][h2] * eu_s[l + h2][tid];
            float bu = accu * invM;
            __stcg(&d_betau[b][l][r][tid], bu);
            ownBu[W - 2][tid] = bu;
            if (W == Nn) {   // only block (b, 0): fused root reduction
                float v = bu * __expf(root[b * NTT + tid]);
                #pragma unroll
                for (int o = 8; o > 0; o >>= 1) v += __shfl_xor_sync(0xffffu, v, o);
                if (tid == 0) out[b] = srefF + logf(Msm) + logf(v);
            }
        }
        float ss = 0.f;
        if (tid == 0) {
            ss = srefF + logf(Msm);
            ownS[W] = ss;
        }
        __syncthreads();   // bar 4: all stores + ownS ordered before release
        if (tid == 0) st_release_gpu(&d_Ssc[b][l][r], ss);
        if (tid == 32) Msm_u = 0u;   // ordered for consumers by next cell's barriers
    }
}

// ---------------- launch ----------------
extern "C" void kernel_launch(void* const* d_in, const int* in_sizes, int n_in,
                              void* d_out, int out_size) {
    const float* unary = nullptr;
    const float* rule  = nullptr;
    const float* root  = nullptr;
    for (int i = 0; i < n_in; i++) {
        if (in_sizes[i] == Bv * Nn * TT)                      unary = (const float*)d_in[i];
        else if (in_sizes[i] == Bv * NTT * Nn * TT * TT * 2)  rule  = (const float*)d_in[i];
        else if (in_sizes[i] == Bv * NTT)                     root  = (const float*)d_in[i];
    }

    int dynBytes = (2 * 24 * 264 + 23 * 16 * 24) * (int)sizeof(float);  // 86016
    cudaFuncSetAttribute(k_chart, cudaFuncAttributeMaxDynamicSharedMemorySize, dynBytes);

    k_pre<<<Bv * NTT * Nn, 256>>>(rule, unary);
    k_chart<<<Bv * NL, THR, dynBytes>>>(unary, root, (float*)d_out);
}